// round 12
// baseline (speedup 1.0000x reference)
#include <cuda_runtime.h>
#include <cuda_fp16.h>
#include <stdint.h>
#include <float.h>

#define NROWS   65536
#define DIMS    256
#define NCODES  1024
#define TM      128        // rows per block
#define TC      64         // codes per chunk
#define NCHUNK  (NCODES / TC)
#define MARGIN  2e-3f      // ~7 sigma of f16-acc distance error; R6/R11-proven value
#define ASTRB   528        // f16 row stride bytes -> conflict-free ldmatrix

// ---- smem layout (bytes) -------------------------------------------------
#define OFF_A      0                         // 128 x 528                 67584
#define OFF_B      67584                     // 64 x 528                  33792
// aliased into B region (only used AFTER the chunk loop):
#define OFF_FMIN   67584                     // i32[128]                    512
#define OFF_BEST   68096                     // u64[128]                   1024
#define OFF_IDX    69120                     // i32[128]                    512
#define OFF_ROVF   69632                     // i32[128]                    512
#define OFF_OVFL   70144                     // i32 count + i32[128]        520
#define OFF_RED    70664                     // double[256]                2048
// persistent:
#define OFF_E2     101376                    // f32[1024]                  4096
#define OFF_Z2     105472                    // f32[128]                    512
#define SMEM_BYTES 105984

__device__ float          g_e2[NCODES];
__device__ unsigned short g_ehf[NCODES * DIMS];   // f16 codebook (pre-converted)
__device__ double         g_loss_accum;

// ---------------------------------------------------------------------------
__device__ __forceinline__ uint32_t smem_u32(const void* p) {
    uint32_t a;
    asm("{ .reg .u64 t; cvta.to.shared.u64 t, %1; cvt.u32.u64 %0, t; }"
        : "=r"(a) : "l"(p));
    return a;
}
__device__ __forceinline__ void ldm_x4(uint32_t* r, uint32_t a) {
    asm volatile("ldmatrix.sync.aligned.m8n8.x4.shared.b16 {%0,%1,%2,%3}, [%4];"
                 : "=r"(r[0]), "=r"(r[1]), "=r"(r[2]), "=r"(r[3]) : "r"(a));
}
// f16 x f16 -> f16 accumulators (2 packed regs)
__device__ __forceinline__ void mma_f16(uint32_t* c, const uint32_t* a,
                                        const uint32_t* b) {
    asm volatile(
        "mma.sync.aligned.m16n8k16.row.col.f16.f16.f16.f16 "
        "{%0,%1},{%2,%3,%4,%5},{%6,%7},{%0,%1};"
        : "+r"(c[0]), "+r"(c[1])
        : "r"(a[0]), "r"(a[1]), "r"(a[2]), "r"(a[3]), "r"(b[0]), "r"(b[1]));
}

// ---------------------------------------------------------------------------
// prep: per-code e2 + f16 codebook + loss zeroing (one warp per code)
// ---------------------------------------------------------------------------
__global__ void vq_prep(const float* __restrict__ emb) {
    if (blockIdx.x == 0 && threadIdx.x == 0) g_loss_accum = 0.0;
    int warp = (blockIdx.x * blockDim.x + threadIdx.x) >> 5;
    int lane = threadIdx.x & 31;
    if (warp < NCODES) {
        const float* row = emb + warp * DIMS;
        float s = 0.f;
#pragma unroll
        for (int i = 0; i < DIMS / 32; i++) {
            float v = row[lane + 32 * i];
            s = __fadd_rn(s, __fmul_rn(v, v));
        }
#pragma unroll
        for (int o = 16; o > 0; o >>= 1)
            s = __fadd_rn(s, __shfl_down_sync(0xffffffffu, s, o));
        if (lane == 0) g_e2[warp] = s;
        unsigned short q[8];
#pragma unroll
        for (int j = 0; j < 8; j++) {
            __half h = __float2half_rn(row[lane * 8 + j]);
            q[j] = *(unsigned short*)&h;
        }
        *(uint4*)(g_ehf + (size_t)warp * DIMS + lane * 8) = *(uint4*)q;
    }
}

// stage one 64-code f16 chunk: pure 16B copy, fully coalesced
__device__ __forceinline__ void stage_B(int chunkBase, char* bt, int tid) {
#pragma unroll
    for (int s = 0; s < 8; s++) {
        int idx = tid + s * 256;
        int cc  = idx >> 5;
        int seg = idx & 31;
        uint4 v = *(const uint4*)(g_ehf + (size_t)(chunkBase + cc) * DIMS + seg * 8);
        *(uint4*)(bt + (size_t)cc * ASTRB + seg * 16) = v;
    }
}

// canonical exact fp32 distance (R1-proven formula/rounding) + tiebreak pack
__device__ __forceinline__ unsigned long long exact_dist(
    const float* __restrict__ zrow, const float* __restrict__ emb,
    int code, float z2, const float* __restrict__ e2all) {
    const float4* zr = (const float4*)zrow;
    const float4* er = (const float4*)(emb + (size_t)code * DIMS);
    float d0 = 0.f, d1 = 0.f, d2 = 0.f, d3 = 0.f;
#pragma unroll 8
    for (int k4 = 0; k4 < DIMS / 4; k4++) {
        float4 zv = __ldg(&zr[k4]);
        float4 ev = __ldg(&er[k4]);
        d0 = fmaf(zv.x, ev.x, d0);
        d1 = fmaf(zv.y, ev.y, d1);
        d2 = fmaf(zv.z, ev.z, d2);
        d3 = fmaf(zv.w, ev.w, d3);
    }
    float dot  = __fadd_rn(__fadd_rn(d0, d1), __fadd_rn(d2, d3));
    float t    = __fadd_rn(z2, e2all[code]);
    float dist = __fsub_rn(t, __fmul_rn(2.0f, dot));
    return ((unsigned long long)__float_as_uint(dist) << 32) | (unsigned)code;
}

// ---------------------------------------------------------------------------
__global__ void __launch_bounds__(256, 2)
vq_main(const float* __restrict__ z, const float* __restrict__ emb,
        float* __restrict__ out) {
    extern __shared__ char sm[];
    float*  e2s   = (float*)(sm + OFF_E2);
    float*  z2sm  = (float*)(sm + OFF_Z2);
    int*    fminI = (int*)(sm + OFF_FMIN);
    unsigned long long* bestU = (unsigned long long*)(sm + OFF_BEST);
    int*    idxs  = (int*)(sm + OFF_IDX);
    int*    rowOvf= (int*)(sm + OFF_ROVF);
    int*    ovfl  = (int*)(sm + OFF_OVFL);
    double* red   = (double*)(sm + OFF_RED);

    const int tid  = threadIdx.x;
    const int lane = tid & 31;
    const int warp = tid >> 5;
    const int wr   = warp >> 1;          // rows wr*32 .. +31
    const int wc   = warp & 1;           // codes wc*32 .. +31 within chunk
    const int g    = lane >> 2;          // 0..7
    const int colb = (lane & 3) * 2;
    const int rowBase = blockIdx.x * TM;
    const float* zblk = z + (size_t)rowBase * DIMS;
    const uint32_t smb = smem_u32(sm);

    // ---- stage A (z tile, fp32->f16 once, padded row-major) ----
#pragma unroll 4
    for (int i = tid; i < TM * (DIMS / 4); i += 256) {
        int r  = i >> 6;
        int k4 = i & 63;
        float4 v = __ldg(&((const float4*)zblk)[(size_t)r * (DIMS / 4) + k4]);
        __half2 lo = __float22half2_rn(make_float2(v.x, v.y));
        __half2 hi = __float22half2_rn(make_float2(v.z, v.w));
        uint2 val = make_uint2(*(uint32_t*)&lo, *(uint32_t*)&hi);
        *(uint2*)(sm + OFF_A + (size_t)r * ASTRB + k4 * 8) = val;
    }
    for (int i = tid; i < NCODES; i += 256) e2s[i] = g_e2[i];
    if (tid < TM) {
        const float4* zr = (const float4*)(zblk + (size_t)tid * DIMS);
        float s = 0.f;
        for (int k4 = 0; k4 < DIMS / 4; k4++) {
            float4 v = __ldg(&zr[k4]);
            s = __fadd_rn(s, __fmul_rn(v.x, v.x));
            s = __fadd_rn(s, __fmul_rn(v.y, v.y));
            s = __fadd_rn(s, __fmul_rn(v.z, v.z));
            s = __fadd_rn(s, __fmul_rn(v.w, v.w));
        }
        z2sm[tid] = s;
    }
    __syncthreads();

    // ---- per-lane ldmatrix base addresses (R6-verified mapping) ----
    const uint32_t aBase0 = smb + OFF_A +
        (uint32_t)((wr * 32 + (lane & 15)) * ASTRB) + (lane >> 4) * 16;
    const uint32_t aBase1 = aBase0 + 16 * ASTRB;
    const int brow = (lane & 7) + ((lane & 16) >> 1);
    const uint32_t bBase0 = smb + OFF_B +
        (uint32_t)((wc * 32 + brow) * ASTRB) + ((lane >> 3) & 1) * 16;
    const uint32_t bBase1 = bBase0 + 16 * ASTRB;

    float z2sl[4];
#pragma unroll
    for (int s = 0; s < 4; s++) z2sl[s] = z2sm[wr * 32 + s * 8 + g];

    // per-slot top-3 tracking (values; codes for top-2)
    float b1[4], b2[4], b3[4];
    int   c1[4], c2[4];
#pragma unroll
    for (int s = 0; s < 4; s++) {
        b1[s] = FLT_MAX; b2[s] = FLT_MAX; b3[s] = FLT_MAX;
        c1[s] = 0; c2[s] = 0;
    }

    // ============ chunk loop: f16 HMMA (f16 acc) + top-3 tracking ==========
    for (int c = 0; c < NCHUNK; c++) {
        if (c) __syncthreads();           // prev chunk's B readers done
        stage_B(c * TC, sm + OFF_B, tid);
        __syncthreads();                  // B ready

        uint32_t acc[2][4][2];            // f16x2 accumulators
#pragma unroll
        for (int m = 0; m < 2; m++)
#pragma unroll
            for (int n = 0; n < 4; n++) {
                acc[m][n][0] = 0u;
                acc[m][n][1] = 0u;
            }

#pragma unroll
        for (int ks = 0; ks < 16; ks++) {
            const uint32_t ko = ks * 32;
            uint32_t A0[4], A1[4], B01[4], B23[4];
            ldm_x4(A0, aBase0 + ko);
            ldm_x4(A1, aBase1 + ko);
            ldm_x4(B01, bBase0 + ko);
            ldm_x4(B23, bBase1 + ko);
            mma_f16(acc[0][0], A0, &B01[0]);
            mma_f16(acc[0][1], A0, &B01[2]);
            mma_f16(acc[0][2], A0, &B23[0]);
            mma_f16(acc[0][3], A0, &B23[2]);
            mma_f16(acc[1][0], A1, &B01[0]);
            mma_f16(acc[1][1], A1, &B01[2]);
            mma_f16(acc[1][2], A1, &B23[0]);
            mma_f16(acc[1][3], A1, &B23[2]);
        }

        // tail: distances, slot min, rare top-3 update (skip if smin >= b3)
        float t_e2[8];
#pragma unroll
        for (int n = 0; n < 4; n++) {
            t_e2[n * 2]     = e2s[c * TC + wc * 32 + n * 8 + colb];
            t_e2[n * 2 + 1] = e2s[c * TC + wc * 32 + n * 8 + colb + 1];
        }
        const int cBase = c * TC + wc * 32 + colb;
#pragma unroll
        for (int m = 0; m < 2; m++)
#pragma unroll
            for (int h = 0; h < 2; h++) {     // h: row g (0) / row g+8 (1)
                const int slot = m * 2 + h;
                const float z2e = z2sl[slot];
                float kv[8];
                float smin = FLT_MAX;
#pragma unroll
                for (int n = 0; n < 4; n++) {
                    float2 f = __half22float2(
                        *(const __half2*)&acc[m][n][h]);
                    float da0 = fmaf(-2.f, f.x, z2e + t_e2[n * 2]);
                    float da1 = fmaf(-2.f, f.y, z2e + t_e2[n * 2 + 1]);
                    kv[n * 2]     = da0;
                    kv[n * 2 + 1] = da1;
                    smin = fminf(smin, fminf(da0, da1));
                }
                if (smin < b3[slot]) {
#pragma unroll
                    for (int q = 0; q < 8; q++) {
                        float v = kv[q];
                        int   code = cBase + (q >> 1) * 8 + (q & 1);
                        if (v < b1[slot]) {
                            b3[slot] = b2[slot];
                            b2[slot] = b1[slot]; c2[slot] = c1[slot];
                            b1[slot] = v;        c1[slot] = code;
                        } else if (v < b2[slot]) {
                            b3[slot] = b2[slot];
                            b2[slot] = v;        c2[slot] = code;
                        } else if (v < b3[slot]) {
                            b3[slot] = v;
                        }
                    }
                }
            }
    }
    __syncthreads();                      // chunk loop done; B region reusable

    // ---- init aliased post-loop state ----
    if (tid < TM) {
        fminI[tid]  = 0x7f800000;
        bestU[tid]  = ~0ull;
        rowOvf[tid] = 0;
    }
    if (tid == 0) ovfl[0] = 0;
    __syncthreads();

#pragma unroll
    for (int s = 0; s < 4; s++)
        atomicMin(&fminI[wr * 32 + s * 8 + g], __float_as_int(b1[s]));
    __syncthreads();

    // ---- rescore top-2 candidates; flag rows needing full scan ----
#pragma unroll
    for (int s = 0; s < 4; s++) {
        const int row = wr * 32 + s * 8 + g;
        const float thr = __int_as_float(fminI[row]) + MARGIN;
        if (b1[s] <= thr)
            atomicMin(&bestU[row],
                      exact_dist(zblk + (size_t)row * DIMS, emb, c1[s],
                                 z2sm[row], e2s));
        if (b2[s] <= thr)
            atomicMin(&bestU[row],
                      exact_dist(zblk + (size_t)row * DIMS, emb, c2[s],
                                 z2sm[row], e2s));
        if (b3[s] <= thr) rowOvf[row] = 1;
    }
    __syncthreads();

    // ---- overflow rows: full exact scan (safety net, ~never taken) ----
    if (tid < TM && rowOvf[tid]) {
        int p = atomicAdd(&ovfl[0], 1);
        ovfl[1 + p] = tid;
    }
    __syncthreads();
    int novf = ovfl[0];
    for (int f = 0; f < novf; f++) {
        int row = ovfl[1 + f];
        float z2r = z2sm[row];
        for (int code = tid; code < NCODES; code += 256) {
            unsigned long long p =
                exact_dist(zblk + (size_t)row * DIMS, emb, code, z2r, e2s);
            atomicMin(&bestU[row], p);
        }
    }
    if (novf) __syncthreads();

    if (tid < TM) idxs[tid] = (int)(bestU[tid] & 0xffffffffull);
    __syncthreads();

    // ================= epilogue: gather / STE / loss ======================
    double lsum = 0.0;
    float* outblk = out + (size_t)rowBase * DIMS;
#pragma unroll 4
    for (int i = tid; i < TM * (DIMS / 4); i += 256) {
        int r  = i >> 6;
        int k4 = i & 63;
        float4 zv = __ldg(&((const float4*)zblk)[(size_t)r * (DIMS / 4) + k4]);
        float4 qv = __ldg(&((const float4*)(emb + (size_t)idxs[r] * DIMS))[k4]);
        float4 ov; float d;
        d = __fsub_rn(qv.x, zv.x); ov.x = __fadd_rn(zv.x, d); lsum += (double)__fmul_rn(d, d);
        d = __fsub_rn(qv.y, zv.y); ov.y = __fadd_rn(zv.y, d); lsum += (double)__fmul_rn(d, d);
        d = __fsub_rn(qv.z, zv.z); ov.z = __fadd_rn(zv.z, d); lsum += (double)__fmul_rn(d, d);
        d = __fsub_rn(qv.w, zv.w); ov.w = __fadd_rn(zv.w, d); lsum += (double)__fmul_rn(d, d);
        ((float4*)outblk)[i] = ov;
    }
    red[tid] = lsum;
    __syncthreads();
    for (int s = 128; s > 0; s >>= 1) {
        if (tid < s) red[tid] += red[tid + s];
        __syncthreads();
    }
    if (tid == 0) atomicAdd(&g_loss_accum, red[0]);
}

// ---------------------------------------------------------------------------
__global__ void vq_finalize(float* __restrict__ out, int out_size) {
    double mean = g_loss_accum / (double)((size_t)NROWS * DIMS);
    float loss = (float)(0.5 * mean);
    out[out_size - 2] = loss;   // commitment_loss
    out[out_size - 1] = loss;   // emb_loss
}

// ---------------------------------------------------------------------------
extern "C" void kernel_launch(void* const* d_in, const int* in_sizes, int n_in,
                              void* d_out, int out_size) {
    const float* z   = (const float*)d_in[0];
    const float* emb = (const float*)d_in[1];
    if (n_in >= 2 && in_sizes[0] == NCODES * DIMS && in_sizes[1] == NROWS * DIMS) {
        emb = (const float*)d_in[0];
        z   = (const float*)d_in[1];
    }
    float* out = (float*)d_out;

    vq_prep<<<(NCODES * 32 + 255) / 256, 256>>>(emb);

    cudaFuncSetAttribute(vq_main, cudaFuncAttributeMaxDynamicSharedMemorySize,
                         SMEM_BYTES);
    vq_main<<<NROWS / TM, 256, SMEM_BYTES>>>(z, emb, out);

    vq_finalize<<<1, 1>>>(out, out_size);
}

// round 13
// speedup vs baseline: 1.0538x; 1.0538x over previous
#include <cuda_runtime.h>
#include <cuda_fp16.h>
#include <stdint.h>
#include <float.h>

#define NROWS   65536
#define DIMS    256
#define NCODES  1024
#define TM      128        // rows per block
#define TC      64         // codes per chunk
#define NCHUNK  (NCODES / TC)
#define MARGIN  2e-3f      // R12-proven for f16-acc pipeline
#define ASTRB   528        // f16 row stride bytes -> conflict-free ldmatrix

// ---- smem layout (bytes) -------------------------------------------------
#define OFF_A      0                         // 128 x 528                 67584
#define OFF_B      67584                     // 64 x 528                  33792
// aliased into B region (only used AFTER the chunk loop):
#define OFF_FMIN   67584                     // i32[128]                    512
#define OFF_BEST   68096                     // u64[128]                   1024
#define OFF_IDX    69120                     // i32[128]                    512
#define OFF_ROVF   69632                     // i32[128]                    512
#define OFF_OVFL   70144                     // i32 count + i32[128]        520
#define OFF_RED    70664                     // double[256]                2048
// persistent:
#define OFF_E2     101376                    // f32[1024]                  4096
#define OFF_Z2     105472                    // f32[128]                    512
#define SMEM_BYTES 105984

__device__ float          g_e2[NCODES];
__device__ unsigned short g_ehf[NCODES * DIMS];   // f16 codebook (pre-converted)
__device__ double         g_loss_accum;

// ---------------------------------------------------------------------------
__device__ __forceinline__ uint32_t smem_u32(const void* p) {
    uint32_t a;
    asm("{ .reg .u64 t; cvta.to.shared.u64 t, %1; cvt.u32.u64 %0, t; }"
        : "=r"(a) : "l"(p));
    return a;
}
__device__ __forceinline__ void ldm_x4(uint32_t* r, uint32_t a) {
    asm volatile("ldmatrix.sync.aligned.m8n8.x4.shared.b16 {%0,%1,%2,%3}, [%4];"
                 : "=r"(r[0]), "=r"(r[1]), "=r"(r[2]), "=r"(r[3]) : "r"(a));
}
// f16 x f16 -> f16 accumulators (2 packed regs)
__device__ __forceinline__ void mma_f16(uint32_t* c, const uint32_t* a,
                                        const uint32_t* b) {
    asm volatile(
        "mma.sync.aligned.m16n8k16.row.col.f16.f16.f16.f16 "
        "{%0,%1},{%2,%3,%4,%5},{%6,%7},{%0,%1};"
        : "+r"(c[0]), "+r"(c[1])
        : "r"(a[0]), "r"(a[1]), "r"(a[2]), "r"(a[3]), "r"(b[0]), "r"(b[1]));
}

// ---------------------------------------------------------------------------
// prep: per-code e2 + f16 codebook + loss zeroing (one warp per code)
// ---------------------------------------------------------------------------
__global__ void vq_prep(const float* __restrict__ emb) {
    if (blockIdx.x == 0 && threadIdx.x == 0) g_loss_accum = 0.0;
    int warp = (blockIdx.x * blockDim.x + threadIdx.x) >> 5;
    int lane = threadIdx.x & 31;
    if (warp < NCODES) {
        const float* row = emb + warp * DIMS;
        float s = 0.f;
#pragma unroll
        for (int i = 0; i < DIMS / 32; i++) {
            float v = row[lane + 32 * i];
            s = __fadd_rn(s, __fmul_rn(v, v));
        }
#pragma unroll
        for (int o = 16; o > 0; o >>= 1)
            s = __fadd_rn(s, __shfl_down_sync(0xffffffffu, s, o));
        if (lane == 0) g_e2[warp] = s;
        unsigned short q[8];
#pragma unroll
        for (int j = 0; j < 8; j++) {
            __half h = __float2half_rn(row[lane * 8 + j]);
            q[j] = *(unsigned short*)&h;
        }
        *(uint4*)(g_ehf + (size_t)warp * DIMS + lane * 8) = *(uint4*)q;
    }
}

// canonical exact fp32 distance (R1-proven formula/rounding) + tiebreak pack
__device__ __forceinline__ unsigned long long exact_dist(
    const float* __restrict__ zrow, const float* __restrict__ emb,
    int code, float z2, const float* __restrict__ e2all) {
    const float4* zr = (const float4*)zrow;
    const float4* er = (const float4*)(emb + (size_t)code * DIMS);
    float d0 = 0.f, d1 = 0.f, d2 = 0.f, d3 = 0.f;
#pragma unroll 8
    for (int k4 = 0; k4 < DIMS / 4; k4++) {
        float4 zv = __ldg(&zr[k4]);
        float4 ev = __ldg(&er[k4]);
        d0 = fmaf(zv.x, ev.x, d0);
        d1 = fmaf(zv.y, ev.y, d1);
        d2 = fmaf(zv.z, ev.z, d2);
        d3 = fmaf(zv.w, ev.w, d3);
    }
    float dot  = __fadd_rn(__fadd_rn(d0, d1), __fadd_rn(d2, d3));
    float t    = __fadd_rn(z2, e2all[code]);
    float dist = __fsub_rn(t, __fmul_rn(2.0f, dot));
    return ((unsigned long long)__float_as_uint(dist) << 32) | (unsigned)code;
}

// ---------------------------------------------------------------------------
__global__ void __launch_bounds__(256, 2)
vq_main(const float* __restrict__ z, const float* __restrict__ emb,
        float* __restrict__ out) {
    extern __shared__ char sm[];
    float*  e2s   = (float*)(sm + OFF_E2);
    float*  z2sm  = (float*)(sm + OFF_Z2);
    int*    fminI = (int*)(sm + OFF_FMIN);
    unsigned long long* bestU = (unsigned long long*)(sm + OFF_BEST);
    int*    idxs  = (int*)(sm + OFF_IDX);
    int*    rowOvf= (int*)(sm + OFF_ROVF);
    int*    ovfl  = (int*)(sm + OFF_OVFL);
    double* red   = (double*)(sm + OFF_RED);

    const int tid  = threadIdx.x;
    const int lane = tid & 31;
    const int warp = tid >> 5;
    const int wr   = warp >> 1;          // rows wr*32 .. +31
    const int wc   = warp & 1;           // codes wc*32 .. +31 within chunk
    const int g    = lane >> 2;          // 0..7
    const int colb = (lane & 3) * 2;
    const int rowBase = blockIdx.x * TM;
    const float* zblk = z + (size_t)rowBase * DIMS;
    const uint32_t smb = smem_u32(sm);

    // this thread's 8 staging segments (fixed across chunks)
    const int stg_c   = tid >> 5;                // base code row (+8s per seg? no:)
    // segments: idx = tid + s*256 ; cc = idx>>5 ; seg = idx&31
    // For tid fixed, s varies: cc = (tid + s*256)>>5 = (tid>>5) + s*8, seg = tid&31.
    const int stg_seg = tid & 31;

    // ---- stage A (z tile, fp32->f16 once, padded row-major) ----
#pragma unroll 4
    for (int i = tid; i < TM * (DIMS / 4); i += 256) {
        int r  = i >> 6;
        int k4 = i & 63;
        float4 v = __ldg(&((const float4*)zblk)[(size_t)r * (DIMS / 4) + k4]);
        __half2 lo = __float22half2_rn(make_float2(v.x, v.y));
        __half2 hi = __float22half2_rn(make_float2(v.z, v.w));
        uint2 val = make_uint2(*(uint32_t*)&lo, *(uint32_t*)&hi);
        *(uint2*)(sm + OFF_A + (size_t)r * ASTRB + k4 * 8) = val;
    }
    for (int i = tid; i < NCODES; i += 256) e2s[i] = g_e2[i];
    if (tid < TM) {
        const float4* zr = (const float4*)(zblk + (size_t)tid * DIMS);
        float s = 0.f;
        for (int k4 = 0; k4 < DIMS / 4; k4++) {
            float4 v = __ldg(&zr[k4]);
            s = __fadd_rn(s, __fmul_rn(v.x, v.x));
            s = __fadd_rn(s, __fmul_rn(v.y, v.y));
            s = __fadd_rn(s, __fmul_rn(v.z, v.z));
            s = __fadd_rn(s, __fmul_rn(v.w, v.w));
        }
        z2sm[tid] = s;
    }
    // stage B chunk 0 directly
    {
#pragma unroll
        for (int s = 0; s < 8; s++) {
            int cc = (tid >> 5) + s * 8;
            uint4 v = *(const uint4*)(g_ehf + (size_t)cc * DIMS + stg_seg * 8);
            *(uint4*)(sm + OFF_B + (size_t)cc * ASTRB + stg_seg * 16) = v;
        }
    }
    __syncthreads();

    // ---- per-lane ldmatrix base addresses (R6-verified mapping) ----
    const uint32_t aBase0 = smb + OFF_A +
        (uint32_t)((wr * 32 + (lane & 15)) * ASTRB) + (lane >> 4) * 16;
    const uint32_t aBase1 = aBase0 + 16 * ASTRB;
    const int brow = (lane & 7) + ((lane & 16) >> 1);
    const uint32_t bBase0 = smb + OFF_B +
        (uint32_t)((wc * 32 + brow) * ASTRB) + ((lane >> 3) & 1) * 16;
    const uint32_t bBase1 = bBase0 + 16 * ASTRB;

    float z2sl[4];
#pragma unroll
    for (int s = 0; s < 4; s++) z2sl[s] = z2sm[wr * 32 + s * 8 + g];

    // per-slot top-3 tracking (values; codes for top-2)
    float b1[4], b2[4], b3[4];
    int   c1[4], c2[4];
#pragma unroll
    for (int s = 0; s < 4; s++) {
        b1[s] = FLT_MAX; b2[s] = FLT_MAX; b3[s] = FLT_MAX;
        c1[s] = 0; c2[s] = 0;
    }

    // ====== chunk loop: f16 HMMA + top-3 tracking + register prefetch ======
    for (int c = 0; c < NCHUNK; c++) {
        // issue next chunk's LDGs first: latency overlaps the MMA block below
        uint4 pf[8];
        if (c + 1 < NCHUNK) {
            const int nb = (c + 1) * TC;
#pragma unroll
            for (int s = 0; s < 8; s++) {
                int cc = (tid >> 5) + s * 8;
                pf[s] = *(const uint4*)(g_ehf + (size_t)(nb + cc) * DIMS +
                                        stg_seg * 8);
            }
        }

        uint32_t acc[2][4][2];            // f16x2 accumulators
#pragma unroll
        for (int m = 0; m < 2; m++)
#pragma unroll
            for (int n = 0; n < 4; n++) {
                acc[m][n][0] = 0u;
                acc[m][n][1] = 0u;
            }

#pragma unroll
        for (int ks = 0; ks < 16; ks++) {
            const uint32_t ko = ks * 32;
            uint32_t A0[4], A1[4], B01[4], B23[4];
            ldm_x4(A0, aBase0 + ko);
            ldm_x4(A1, aBase1 + ko);
            ldm_x4(B01, bBase0 + ko);
            ldm_x4(B23, bBase1 + ko);
            mma_f16(acc[0][0], A0, &B01[0]);
            mma_f16(acc[0][1], A0, &B01[2]);
            mma_f16(acc[0][2], A0, &B23[0]);
            mma_f16(acc[0][3], A0, &B23[2]);
            mma_f16(acc[1][0], A1, &B01[0]);
            mma_f16(acc[1][1], A1, &B01[2]);
            mma_f16(acc[1][2], A1, &B23[0]);
            mma_f16(acc[1][3], A1, &B23[2]);
        }

        // tail: distances, slot min, rare top-3 update (skip if smin >= b3)
        float t_e2[8];
#pragma unroll
        for (int n = 0; n < 4; n++) {
            t_e2[n * 2]     = e2s[c * TC + wc * 32 + n * 8 + colb];
            t_e2[n * 2 + 1] = e2s[c * TC + wc * 32 + n * 8 + colb + 1];
        }
        const int cBase = c * TC + wc * 32 + colb;
#pragma unroll
        for (int m = 0; m < 2; m++)
#pragma unroll
            for (int h = 0; h < 2; h++) {     // h: row g (0) / row g+8 (1)
                const int slot = m * 2 + h;
                const float z2e = z2sl[slot];
                float kv[8];
                float smin = FLT_MAX;
#pragma unroll
                for (int n = 0; n < 4; n++) {
                    float2 f = __half22float2(
                        *(const __half2*)&acc[m][n][h]);
                    float da0 = fmaf(-2.f, f.x, z2e + t_e2[n * 2]);
                    float da1 = fmaf(-2.f, f.y, z2e + t_e2[n * 2 + 1]);
                    kv[n * 2]     = da0;
                    kv[n * 2 + 1] = da1;
                    smin = fminf(smin, fminf(da0, da1));
                }
                if (smin < b3[slot]) {
#pragma unroll
                    for (int q = 0; q < 8; q++) {
                        float v = kv[q];
                        int   code = cBase + (q >> 1) * 8 + (q & 1);
                        if (v < b1[slot]) {
                            b3[slot] = b2[slot];
                            b2[slot] = b1[slot]; c2[slot] = c1[slot];
                            b1[slot] = v;        c1[slot] = code;
                        } else if (v < b2[slot]) {
                            b3[slot] = b2[slot];
                            b2[slot] = v;        c2[slot] = code;
                        } else if (v < b3[slot]) {
                            b3[slot] = v;
                        }
                    }
                }
            }

        if (c + 1 < NCHUNK) {
            __syncthreads();              // all readers of B done
#pragma unroll
            for (int s = 0; s < 8; s++) {
                int cc = (tid >> 5) + s * 8;
                *(uint4*)(sm + OFF_B + (size_t)cc * ASTRB + stg_seg * 16) = pf[s];
            }
            __syncthreads();              // B ready
        }
    }
    __syncthreads();                      // chunk loop done; B region reusable

    // ---- init aliased post-loop state ----
    if (tid < TM) {
        fminI[tid]  = 0x7f800000;
        bestU[tid]  = ~0ull;
        rowOvf[tid] = 0;
    }
    if (tid == 0) ovfl[0] = 0;
    __syncthreads();

#pragma unroll
    for (int s = 0; s < 4; s++)
        atomicMin(&fminI[wr * 32 + s * 8 + g], __float_as_int(b1[s]));
    __syncthreads();

    // ---- rescore top-2 candidates; flag rows needing full scan ----
#pragma unroll
    for (int s = 0; s < 4; s++) {
        const int row = wr * 32 + s * 8 + g;
        const float thr = __int_as_float(fminI[row]) + MARGIN;
        if (b1[s] <= thr)
            atomicMin(&bestU[row],
                      exact_dist(zblk + (size_t)row * DIMS, emb, c1[s],
                                 z2sm[row], e2s));
        if (b2[s] <= thr)
            atomicMin(&bestU[row],
                      exact_dist(zblk + (size_t)row * DIMS, emb, c2[s],
                                 z2sm[row], e2s));
        if (b3[s] <= thr) rowOvf[row] = 1;
    }
    __syncthreads();

    // ---- overflow rows: full exact scan (safety net, ~never taken) ----
    if (tid < TM && rowOvf[tid]) {
        int p = atomicAdd(&ovfl[0], 1);
        ovfl[1 + p] = tid;
    }
    __syncthreads();
    int novf = ovfl[0];
    for (int f = 0; f < novf; f++) {
        int row = ovfl[1 + f];
        float z2r = z2sm[row];
        for (int code = tid; code < NCODES; code += 256) {
            unsigned long long p =
                exact_dist(zblk + (size_t)row * DIMS, emb, code, z2r, e2s);
            atomicMin(&bestU[row], p);
        }
    }
    if (novf) __syncthreads();

    if (tid < TM) idxs[tid] = (int)(bestU[tid] & 0xffffffffull);
    __syncthreads();

    // ================= epilogue: gather / STE / loss ======================
    double lsum = 0.0;
    float* outblk = out + (size_t)rowBase * DIMS;
#pragma unroll 4
    for (int i = tid; i < TM * (DIMS / 4); i += 256) {
        int r  = i >> 6;
        int k4 = i & 63;
        float4 zv = __ldg(&((const float4*)zblk)[(size_t)r * (DIMS / 4) + k4]);
        float4 qv = __ldg(&((const float4*)(emb + (size_t)idxs[r] * DIMS))[k4]);
        float4 ov; float d;
        d = __fsub_rn(qv.x, zv.x); ov.x = __fadd_rn(zv.x, d); lsum += (double)__fmul_rn(d, d);
        d = __fsub_rn(qv.y, zv.y); ov.y = __fadd_rn(zv.y, d); lsum += (double)__fmul_rn(d, d);
        d = __fsub_rn(qv.z, zv.z); ov.z = __fadd_rn(zv.z, d); lsum += (double)__fmul_rn(d, d);
        d = __fsub_rn(qv.w, zv.w); ov.w = __fadd_rn(zv.w, d); lsum += (double)__fmul_rn(d, d);
        ((float4*)outblk)[i] = ov;
    }
    red[tid] = lsum;
    __syncthreads();
    for (int s = 128; s > 0; s >>= 1) {
        if (tid < s) red[tid] += red[tid + s];
        __syncthreads();
    }
    if (tid == 0) atomicAdd(&g_loss_accum, red[0]);
}

// ---------------------------------------------------------------------------
__global__ void vq_finalize(float* __restrict__ out, int out_size) {
    double mean = g_loss_accum / (double)((size_t)NROWS * DIMS);
    float loss = (float)(0.5 * mean);
    out[out_size - 2] = loss;   // commitment_loss
    out[out_size - 1] = loss;   // emb_loss
}

// ---------------------------------------------------------------------------
extern "C" void kernel_launch(void* const* d_in, const int* in_sizes, int n_in,
                              void* d_out, int out_size) {
    const float* z   = (const float*)d_in[0];
    const float* emb = (const float*)d_in[1];
    if (n_in >= 2 && in_sizes[0] == NCODES * DIMS && in_sizes[1] == NROWS * DIMS) {
        emb = (const float*)d_in[0];
        z   = (const float*)d_in[1];
    }
    float* out = (float*)d_out;

    vq_prep<<<(NCODES * 32 + 255) / 256, 256>>>(emb);

    cudaFuncSetAttribute(vq_main, cudaFuncAttributeMaxDynamicSharedMemorySize,
                         SMEM_BYTES);
    vq_main<<<NROWS / TM, 256, SMEM_BYTES>>>(z, emb, out);

    vq_finalize<<<1, 1>>>(out, out_size);
}

// round 14
// speedup vs baseline: 1.2396x; 1.1763x over previous
#include <cuda_runtime.h>
#include <cuda_fp16.h>
#include <stdint.h>
#include <float.h>

#define NROWS   65536
#define DIMS    256
#define NCODES  1024
#define TM      64         // rows per block
#define TC      64         // codes per chunk
#define NCHUNK  (NCODES / TC)
#define MARGIN  2e-3f      // R12/R13-proven for f16-acc pipeline
#define ASTRB   528        // f16 row stride bytes -> conflict-free ldmatrix

// ---- smem layout (bytes) -------------------------------------------------
#define OFF_A      0                         // 64 x 528                  33792
#define OFF_B      33792                     // 64 x 528                  33792
// aliased into B region (only used AFTER the chunk loop):
#define OFF_FMIN   33792                     // i32[64]                     256
#define OFF_BEST   34048                     // u64[64]                     512
#define OFF_IDX    34560                     // i32[64]                     256
#define OFF_ROVF   34816                     // i32[64]                     256
#define OFF_OVFL   35072                     // i32 count + i32[64]         260
#define OFF_RED    35336                     // double[256]                2048
// persistent:
#define OFF_E2     67584                     // f32[1024]                  4096
#define OFF_Z2     71680                     // f32[64]                     256
#define SMEM_BYTES 71936

__device__ float          g_e2[NCODES];
__device__ unsigned short g_ehf[NCODES * DIMS];   // f16 codebook (pre-converted)
__device__ double         g_loss_accum;

// ---------------------------------------------------------------------------
__device__ __forceinline__ uint32_t smem_u32(const void* p) {
    uint32_t a;
    asm("{ .reg .u64 t; cvta.to.shared.u64 t, %1; cvt.u32.u64 %0, t; }"
        : "=r"(a) : "l"(p));
    return a;
}
__device__ __forceinline__ void ldm_x4(uint32_t* r, uint32_t a) {
    asm volatile("ldmatrix.sync.aligned.m8n8.x4.shared.b16 {%0,%1,%2,%3}, [%4];"
                 : "=r"(r[0]), "=r"(r[1]), "=r"(r[2]), "=r"(r[3]) : "r"(a));
}
// f16 x f16 -> f16 accumulators (2 packed regs)
__device__ __forceinline__ void mma_f16(uint32_t* c, const uint32_t* a,
                                        const uint32_t* b) {
    asm volatile(
        "mma.sync.aligned.m16n8k16.row.col.f16.f16.f16.f16 "
        "{%0,%1},{%2,%3,%4,%5},{%6,%7},{%0,%1};"
        : "+r"(c[0]), "+r"(c[1])
        : "r"(a[0]), "r"(a[1]), "r"(a[2]), "r"(a[3]), "r"(b[0]), "r"(b[1]));
}

// ---------------------------------------------------------------------------
// prep: per-code e2 + f16 codebook + loss zeroing (one warp per code)
// ---------------------------------------------------------------------------
__global__ void vq_prep(const float* __restrict__ emb) {
    if (blockIdx.x == 0 && threadIdx.x == 0) g_loss_accum = 0.0;
    int warp = (blockIdx.x * blockDim.x + threadIdx.x) >> 5;
    int lane = threadIdx.x & 31;
    if (warp < NCODES) {
        const float* row = emb + warp * DIMS;
        float s = 0.f;
#pragma unroll
        for (int i = 0; i < DIMS / 32; i++) {
            float v = row[lane + 32 * i];
            s = __fadd_rn(s, __fmul_rn(v, v));
        }
#pragma unroll
        for (int o = 16; o > 0; o >>= 1)
            s = __fadd_rn(s, __shfl_down_sync(0xffffffffu, s, o));
        if (lane == 0) g_e2[warp] = s;
        unsigned short q[8];
#pragma unroll
        for (int j = 0; j < 8; j++) {
            __half h = __float2half_rn(row[lane * 8 + j]);
            q[j] = *(unsigned short*)&h;
        }
        *(uint4*)(g_ehf + (size_t)warp * DIMS + lane * 8) = *(uint4*)q;
    }
}

// canonical exact fp32 distance (R1-proven formula/rounding) + tiebreak pack
__device__ __forceinline__ unsigned long long exact_dist(
    const float* __restrict__ zrow, const float* __restrict__ emb,
    int code, float z2, const float* __restrict__ e2all) {
    const float4* zr = (const float4*)zrow;
    const float4* er = (const float4*)(emb + (size_t)code * DIMS);
    float d0 = 0.f, d1 = 0.f, d2 = 0.f, d3 = 0.f;
#pragma unroll 8
    for (int k4 = 0; k4 < DIMS / 4; k4++) {
        float4 zv = __ldg(&zr[k4]);
        float4 ev = __ldg(&er[k4]);
        d0 = fmaf(zv.x, ev.x, d0);
        d1 = fmaf(zv.y, ev.y, d1);
        d2 = fmaf(zv.z, ev.z, d2);
        d3 = fmaf(zv.w, ev.w, d3);
    }
    float dot  = __fadd_rn(__fadd_rn(d0, d1), __fadd_rn(d2, d3));
    float t    = __fadd_rn(z2, e2all[code]);
    float dist = __fsub_rn(t, __fmul_rn(2.0f, dot));
    return ((unsigned long long)__float_as_uint(dist) << 32) | (unsigned)code;
}

// ---------------------------------------------------------------------------
__global__ void __launch_bounds__(256, 3)
vq_main(const float* __restrict__ z, const float* __restrict__ emb,
        float* __restrict__ out) {
    extern __shared__ char sm[];
    float*  e2s   = (float*)(sm + OFF_E2);
    float*  z2sm  = (float*)(sm + OFF_Z2);
    int*    fminI = (int*)(sm + OFF_FMIN);
    unsigned long long* bestU = (unsigned long long*)(sm + OFF_BEST);
    int*    idxs  = (int*)(sm + OFF_IDX);
    int*    rowOvf= (int*)(sm + OFF_ROVF);
    int*    ovfl  = (int*)(sm + OFF_OVFL);
    double* red   = (double*)(sm + OFF_RED);

    const int tid  = threadIdx.x;
    const int lane = tid & 31;
    const int warp = tid >> 5;
    const int wr   = warp >> 2;          // 0-1: rows wr*32 .. +31
    const int wc   = warp & 3;           // 0-3: codes wc*16 .. +15 within chunk
    const int g    = lane >> 2;          // 0..7
    const int colb = (lane & 3) * 2;
    const int rowBase = blockIdx.x * TM;
    const float* zblk = z + (size_t)rowBase * DIMS;
    const uint32_t smb = smem_u32(sm);
    const int stg_seg = tid & 31;        // staging: 16B segment

    // ---- stage A (z tile, fp32->f16 once, padded row-major) ----
#pragma unroll 4
    for (int i = tid; i < TM * (DIMS / 4); i += 256) {
        int r  = i >> 6;
        int k4 = i & 63;
        float4 v = __ldg(&((const float4*)zblk)[(size_t)r * (DIMS / 4) + k4]);
        __half2 lo = __float22half2_rn(make_float2(v.x, v.y));
        __half2 hi = __float22half2_rn(make_float2(v.z, v.w));
        uint2 val = make_uint2(*(uint32_t*)&lo, *(uint32_t*)&hi);
        *(uint2*)(sm + OFF_A + (size_t)r * ASTRB + k4 * 8) = val;
    }
    for (int i = tid; i < NCODES; i += 256) e2s[i] = g_e2[i];
    if (tid < TM) {
        const float4* zr = (const float4*)(zblk + (size_t)tid * DIMS);
        float s = 0.f;
        for (int k4 = 0; k4 < DIMS / 4; k4++) {
            float4 v = __ldg(&zr[k4]);
            s = __fadd_rn(s, __fmul_rn(v.x, v.x));
            s = __fadd_rn(s, __fmul_rn(v.y, v.y));
            s = __fadd_rn(s, __fmul_rn(v.z, v.z));
            s = __fadd_rn(s, __fmul_rn(v.w, v.w));
        }
        z2sm[tid] = s;
    }
    __syncthreads();

    // ---- per-lane ldmatrix base addresses (R6-verified mapping) ----
    const uint32_t aBase0 = smb + OFF_A +
        (uint32_t)((wr * 32 + (lane & 15)) * ASTRB) + (lane >> 4) * 16;
    const uint32_t aBase1 = aBase0 + 16 * ASTRB;
    const int brow = (lane & 7) + ((lane & 16) >> 1);   // 0..15
    const uint32_t bBase = smb + OFF_B +
        (uint32_t)((wc * 16 + brow) * ASTRB) + ((lane >> 3) & 1) * 16;

    float z2sl[4];
#pragma unroll
    for (int s = 0; s < 4; s++) z2sl[s] = z2sm[wr * 32 + s * 8 + g];

    // per-slot top-3 tracking (values; codes for top-2)
    float b1[4], b2[4], b3[4];
    int   c1[4], c2[4];
#pragma unroll
    for (int s = 0; s < 4; s++) {
        b1[s] = FLT_MAX; b2[s] = FLT_MAX; b3[s] = FLT_MAX;
        c1[s] = 0; c2[s] = 0;
    }

    // ============ chunk loop: f16 HMMA (f16 acc) + top-3 tracking ==========
    for (int c = 0; c < NCHUNK; c++) {
        if (c) __syncthreads();           // prev chunk's B readers done
        // stage B: 64 codes x 512B, pure 16B copies
#pragma unroll
        for (int s = 0; s < 8; s++) {
            int cc = (tid >> 5) + s * 8;
            uint4 v = *(const uint4*)(g_ehf + (size_t)(c * TC + cc) * DIMS +
                                      stg_seg * 8);
            *(uint4*)(sm + OFF_B + (size_t)cc * ASTRB + stg_seg * 16) = v;
        }
        __syncthreads();                  // B ready

        uint32_t acc[2][2][2];            // [m][n][h] f16x2 accumulators
#pragma unroll
        for (int m = 0; m < 2; m++)
#pragma unroll
            for (int n = 0; n < 2; n++) {
                acc[m][n][0] = 0u;
                acc[m][n][1] = 0u;
            }

#pragma unroll
        for (int ks = 0; ks < 16; ks++) {
            const uint32_t ko = ks * 32;
            uint32_t A0[4], A1[4], B[4];
            ldm_x4(A0, aBase0 + ko);
            ldm_x4(A1, aBase1 + ko);
            ldm_x4(B,  bBase  + ko);
            mma_f16(acc[0][0], A0, &B[0]);
            mma_f16(acc[0][1], A0, &B[2]);
            mma_f16(acc[1][0], A1, &B[0]);
            mma_f16(acc[1][1], A1, &B[2]);
        }

        // tail: distances, slot min, rare top-3 update (skip if smin >= b3)
        float t_e2[4];
#pragma unroll
        for (int n = 0; n < 2; n++) {
            t_e2[n * 2]     = e2s[c * TC + wc * 16 + n * 8 + colb];
            t_e2[n * 2 + 1] = e2s[c * TC + wc * 16 + n * 8 + colb + 1];
        }
        const int cBase = c * TC + wc * 16 + colb;
#pragma unroll
        for (int m = 0; m < 2; m++)
#pragma unroll
            for (int h = 0; h < 2; h++) {     // h: row g (0) / row g+8 (1)
                const int slot = m * 2 + h;
                const float z2e = z2sl[slot];
                float kv[4];
                float smin = FLT_MAX;
#pragma unroll
                for (int n = 0; n < 2; n++) {
                    float2 f = __half22float2(*(const __half2*)&acc[m][n][h]);
                    float da0 = fmaf(-2.f, f.x, z2e + t_e2[n * 2]);
                    float da1 = fmaf(-2.f, f.y, z2e + t_e2[n * 2 + 1]);
                    kv[n * 2]     = da0;
                    kv[n * 2 + 1] = da1;
                    smin = fminf(smin, fminf(da0, da1));
                }
                if (smin < b3[slot]) {
#pragma unroll
                    for (int q = 0; q < 4; q++) {
                        float v = kv[q];
                        int   code = cBase + (q >> 1) * 8 + (q & 1);
                        if (v < b1[slot]) {
                            b3[slot] = b2[slot];
                            b2[slot] = b1[slot]; c2[slot] = c1[slot];
                            b1[slot] = v;        c1[slot] = code;
                        } else if (v < b2[slot]) {
                            b3[slot] = b2[slot];
                            b2[slot] = v;        c2[slot] = code;
                        } else if (v < b3[slot]) {
                            b3[slot] = v;
                        }
                    }
                }
            }
    }
    __syncthreads();                      // chunk loop done; B region reusable

    // ---- init aliased post-loop state ----
    if (tid < TM) {
        fminI[tid]  = 0x7f800000;
        bestU[tid]  = ~0ull;
        rowOvf[tid] = 0;
    }
    if (tid == 0) ovfl[0] = 0;
    __syncthreads();

#pragma unroll
    for (int s = 0; s < 4; s++)
        atomicMin(&fminI[wr * 32 + s * 8 + g], __float_as_int(b1[s]));
    __syncthreads();

    // ---- rescore top-2 candidates; flag rows needing full scan ----
#pragma unroll
    for (int s = 0; s < 4; s++) {
        const int row = wr * 32 + s * 8 + g;
        const float thr = __int_as_float(fminI[row]) + MARGIN;
        if (b1[s] <= thr)
            atomicMin(&bestU[row],
                      exact_dist(zblk + (size_t)row * DIMS, emb, c1[s],
                                 z2sm[row], e2s));
        if (b2[s] <= thr)
            atomicMin(&bestU[row],
                      exact_dist(zblk + (size_t)row * DIMS, emb, c2[s],
                                 z2sm[row], e2s));
        if (b3[s] <= thr) rowOvf[row] = 1;
    }
    __syncthreads();

    // ---- overflow rows: full exact scan (safety net, ~never taken) ----
    if (tid < TM && rowOvf[tid]) {
        int p = atomicAdd(&ovfl[0], 1);
        ovfl[1 + p] = tid;
    }
    __syncthreads();
    int novf = ovfl[0];
    for (int f = 0; f < novf; f++) {
        int row = ovfl[1 + f];
        float z2r = z2sm[row];
        for (int code = tid; code < NCODES; code += 256) {
            unsigned long long p =
                exact_dist(zblk + (size_t)row * DIMS, emb, code, z2r, e2s);
            atomicMin(&bestU[row], p);
        }
    }
    if (novf) __syncthreads();

    if (tid < TM) idxs[tid] = (int)(bestU[tid] & 0xffffffffull);
    __syncthreads();

    // ================= epilogue: gather / STE / loss ======================
    double lsum = 0.0;
    float* outblk = out + (size_t)rowBase * DIMS;
#pragma unroll 4
    for (int i = tid; i < TM * (DIMS / 4); i += 256) {
        int r  = i >> 6;
        int k4 = i & 63;
        float4 zv = __ldg(&((const float4*)zblk)[(size_t)r * (DIMS / 4) + k4]);
        float4 qv = __ldg(&((const float4*)(emb + (size_t)idxs[r] * DIMS))[k4]);
        float4 ov; float d;
        d = __fsub_rn(qv.x, zv.x); ov.x = __fadd_rn(zv.x, d); lsum += (double)__fmul_rn(d, d);
        d = __fsub_rn(qv.y, zv.y); ov.y = __fadd_rn(zv.y, d); lsum += (double)__fmul_rn(d, d);
        d = __fsub_rn(qv.z, zv.z); ov.z = __fadd_rn(zv.z, d); lsum += (double)__fmul_rn(d, d);
        d = __fsub_rn(qv.w, zv.w); ov.w = __fadd_rn(zv.w, d); lsum += (double)__fmul_rn(d, d);
        ((float4*)outblk)[i] = ov;
    }
    red[tid] = lsum;
    __syncthreads();
    for (int s = 128; s > 0; s >>= 1) {
        if (tid < s) red[tid] += red[tid + s];
        __syncthreads();
    }
    if (tid == 0) atomicAdd(&g_loss_accum, red[0]);
}

// ---------------------------------------------------------------------------
__global__ void vq_finalize(float* __restrict__ out, int out_size) {
    double mean = g_loss_accum / (double)((size_t)NROWS * DIMS);
    float loss = (float)(0.5 * mean);
    out[out_size - 2] = loss;   // commitment_loss
    out[out_size - 1] = loss;   // emb_loss
}

// ---------------------------------------------------------------------------
extern "C" void kernel_launch(void* const* d_in, const int* in_sizes, int n_in,
                              void* d_out, int out_size) {
    const float* z   = (const float*)d_in[0];
    const float* emb = (const float*)d_in[1];
    if (n_in >= 2 && in_sizes[0] == NCODES * DIMS && in_sizes[1] == NROWS * DIMS) {
        emb = (const float*)d_in[0];
        z   = (const float*)d_in[1];
    }
    float* out = (float*)d_out;

    vq_prep<<<(NCODES * 32 + 255) / 256, 256>>>(emb);

    cudaFuncSetAttribute(vq_main, cudaFuncAttributeMaxDynamicSharedMemorySize,
                         SMEM_BYTES);
    vq_main<<<NROWS / TM, 256, SMEM_BYTES>>>(z, emb, out);

    vq_finalize<<<1, 1>>>(out, out_size);
}